// round 9
// baseline (speedup 1.0000x reference)
#include <cuda_runtime.h>
#include <cuda_bf16.h>
#include <cstdint>

typedef unsigned int u32;
typedef unsigned long long u64;

#define B_    64
#define IMG   224
#define HW1   112
#define HW2   56
#define FEAT  1024
#define HID   512
#define OUTD  256
#define NC    80

#define APAD  296              // padded K stride in bf16 (592 B, conflict-free)

// ---------------- scratch (static device globals) --------------------------
__device__ __nv_bfloat16 g_conv1b[B_ * HW1 * HW1 * 32];  // NHWC bf16 conv1 out
__device__ __nv_bfloat16 g_wb[64 * APAD];                // conv2 weights bf16 [oc][k]
__device__ float g_pool[B_ * 25 * 64];                   // GAP partials per tile
__device__ int   g_top[B_ * 2];
__device__ float g_A[B_ * 25];
__device__ float g_abar[B_ * 5];
__device__ float g_agg[B_ * 5 * FEAT];
__device__ float g_h1p[128 * 8 * 5 * HID];               // pre-relu h1 partials
__device__ float g_g[B_ * 2 * OUTD];

// ---------------- f32x2 helpers --------------------------------------------
__device__ __forceinline__ u64 pk2(float v) {
    u64 r; asm("mov.b64 %0,{%1,%1};" : "=l"(r) : "f"(v)); return r;
}
__device__ __forceinline__ void upk(u64 v, float& a, float& b) {
    asm("mov.b64 {%0,%1},%2;" : "=f"(a), "=f"(b) : "l"(v));
}
__device__ __forceinline__ void fma2(u64& d, u64 a, u64 b) {
    asm("fma.rn.f32x2 %0,%1,%2,%3;" : "=l"(d) : "l"(a), "l"(b), "l"(d));
}

__device__ __forceinline__ u32 smem_u32(const void* p) {
    u32 a;
    asm("{ .reg .u64 t; cvta.to.shared.u64 t, %1; cvt.u32.u64 %0, t; }"
        : "=r"(a) : "l"(p));
    return a;
}

// ===========================================================================
// K1: conv1 3->32 s2 SAME relu, f32x2 oc-pair packed, output bf16 NHWC.
// Thread = 1 output pixel, 16 u64 accumulators (32 oc).
// ===========================================================================
__global__ __launch_bounds__(224) void k_conv1(const float* __restrict__ x,
                                               const float* __restrict__ w,
                                               const float* __restrict__ bias) {
    __shared__ float sx[3][5][226];
    __shared__ u64   swp[27][16];
    __shared__ float sb[32];
    const int b = blockIdx.y, r0 = blockIdx.x * 2;
    const int tid = threadIdx.x;

    for (int idx = tid; idx < 3 * 5 * 226; idx += 224) {
        int ic = idx / (5 * 226);
        int rem = idx % (5 * 226);
        int rr = rem / 226, col = rem % 226;
        int gr = 2 * r0 + rr;
        float v = 0.f;
        if (gr < IMG && col < IMG) v = x[((b * 3 + ic) * IMG + gr) * IMG + col];
        sx[ic][rr][col] = v;
    }
    for (int idx = tid; idx < 432; idx += 224) {
        int p = idx & 15, ip = idx >> 4;            // ip = ic*9 + kh*3 + kw
        int ic = ip / 9, kh = (ip / 3) % 3, kw = ip % 3;
        float w0 = w[(((2 * p) * 3 + ic) * 3 + kh) * 3 + kw];
        float w1 = w[(((2 * p + 1) * 3 + ic) * 3 + kh) * 3 + kw];
        u64 pk; asm("mov.b64 %0,{%1,%2};" : "=l"(pk) : "f"(w0), "f"(w1));
        swp[ip][p] = pk;
    }
    if (tid < 32) sb[tid] = bias[tid];
    __syncthreads();

    const int rr = tid / 112, c = tid % 112;
    const int r = r0 + rr;
    u64 acc[16];
#pragma unroll
    for (int i = 0; i < 16; i++) acc[i] = 0ULL;

#pragma unroll
    for (int ic = 0; ic < 3; ic++)
#pragma unroll
        for (int kh = 0; kh < 3; kh++) {
            float av[3] = {sx[ic][2 * rr + kh][2 * c],
                           sx[ic][2 * rr + kh][2 * c + 1],
                           sx[ic][2 * rr + kh][2 * c + 2]};
#pragma unroll
            for (int kw = 0; kw < 3; kw++) {
                u64 a2 = pk2(av[kw]);
                const u64* wr = swp[ic * 9 + kh * 3 + kw];
#pragma unroll
                for (int p = 0; p < 16; p++) fma2(acc[p], a2, wr[p]);
            }
        }

    u32 pk[16];
#pragma unroll
    for (int i = 0; i < 16; i++) {
        float a0, a1; upk(acc[i], a0, a1);
        float lo = fmaxf(a0 + sb[2 * i], 0.f);
        float hi = fmaxf(a1 + sb[2 * i + 1], 0.f);
        __nv_bfloat162 t = __floats2bfloat162_rn(lo, hi);
        pk[i] = *(u32*)&t;
    }
    uint4* dst = (uint4*)(g_conv1b + (size_t)((b * HW1 + r) * HW1 + c) * 32);
#pragma unroll
    for (int j = 0; j < 4; j++)
        dst[j] = make_uint4(pk[4 * j], pk[4 * j + 1], pk[4 * j + 2], pk[4 * j + 3]);
}

// ===========================================================================
// K_prep: conv2 weights -> bf16 [oc][k], k = (kh*3+kw)*32 + ic.
// ===========================================================================
__global__ void k_prep(const float* __restrict__ w) {
    const int tid = threadIdx.x;
    for (int idx = tid; idx < 64 * 288; idx += 256) {
        int oc = idx / 288, k = idx % 288;
        int q = k >> 5, ic = k & 31;
        g_wb[oc * APAD + k] = __float2bfloat16(w[oc * 288 + ic * 9 + q]);
    }
}

// ===========================================================================
// K2: conv2 as HMMA GEMM. Block = 128-pixel tile, 8 warps, K=288 im2col.
// ===========================================================================
#define SMA_B   (128 * APAD * 2)
#define SMB_B   (64 * APAD * 2)
#define SMEMC   (SMA_B + SMB_B + 256 + 2048)

__global__ __launch_bounds__(256) void k_conv2(const float* __restrict__ bias) {
    extern __shared__ char sm[];
    char*  smA   = sm;
    char*  smB   = sm + SMA_B;
    float* sbias = (float*)(sm + SMA_B + SMB_B);
    float* spool = (float*)(sm + SMA_B + SMB_B + 256);

    const int b = blockIdx.y, tile = blockIdx.x;
    const int tid = threadIdx.x, wid = tid >> 5, lane = tid & 31;

    for (int t = tid; t < 64 * 9; t += 256) {
        int oc = t / 9, q = t % 9;
        const uint4* src = (const uint4*)(g_wb + oc * APAD + q * 32);
        uint4* dst = (uint4*)(smB + oc * (APAD * 2) + q * 64);
        dst[0] = src[0]; dst[1] = src[1]; dst[2] = src[2]; dst[3] = src[3];
    }
    if (tid < 64) sbias[tid] = bias[tid];

    for (int t = tid; t < 9 * 128; t += 256) {
        int pixel = t & 127, q = t >> 7;
        int kh = q / 3, kw = q % 3;
        int p = tile * 128 + pixel;
        uint4 v0 = {0,0,0,0}, v1 = {0,0,0,0}, v2 = {0,0,0,0}, v3 = {0,0,0,0};
        if (p < 3136) {
            int r = p / 56, c = p - 56 * r;
            int ir = 2 * r + kh, icc = 2 * c + kw;
            if (ir < HW1 && icc < HW1) {
                const uint4* src =
                    (const uint4*)(g_conv1b + (size_t)((b * HW1 + ir) * HW1 + icc) * 32);
                v0 = src[0]; v1 = src[1]; v2 = src[2]; v3 = src[3];
            }
        }
        uint4* dst = (uint4*)(smA + pixel * (APAD * 2) + q * 64);
        dst[0] = v0; dst[1] = v1; dst[2] = v2; dst[3] = v3;
    }
    __syncthreads();

    const int m0 = wid * 16;
    float c[8][4];
#pragma unroll
    for (int i = 0; i < 8; i++)
#pragma unroll
        for (int j = 0; j < 4; j++) c[i][j] = 0.f;

    u32 aaddr = smem_u32(smA) + (m0 + (lane & 15)) * (APAD * 2) + ((lane >> 4) * 16);
    u32 baddr = smem_u32(smB) + ((lane & 7) + ((lane >> 4) & 1) * 8) * (APAD * 2)
              + (((lane >> 3) & 1) * 16);

#pragma unroll 2
    for (int ks = 0; ks < 18; ks++) {
        u32 a0, a1, a2, a3;
        asm volatile("ldmatrix.sync.aligned.m8n8.x4.shared.b16 {%0,%1,%2,%3},[%4];"
                     : "=r"(a0), "=r"(a1), "=r"(a2), "=r"(a3) : "r"(aaddr));
        aaddr += 32;
#pragma unroll
        for (int j = 0; j < 4; j++) {
            u32 b0, b1, b2, b3;
            asm volatile("ldmatrix.sync.aligned.m8n8.x4.shared.b16 {%0,%1,%2,%3},[%4];"
                         : "=r"(b0), "=r"(b1), "=r"(b2), "=r"(b3)
                         : "r"(baddr + j * (16 * APAD * 2)));
            asm volatile(
                "mma.sync.aligned.m16n8k16.row.col.f32.bf16.bf16.f32 "
                "{%0,%1,%2,%3},{%4,%5,%6,%7},{%8,%9},{%0,%1,%2,%3};"
                : "+f"(c[2 * j][0]), "+f"(c[2 * j][1]),
                  "+f"(c[2 * j][2]), "+f"(c[2 * j][3])
                : "r"(a0), "r"(a1), "r"(a2), "r"(a3), "r"(b0), "r"(b1));
            asm volatile(
                "mma.sync.aligned.m16n8k16.row.col.f32.bf16.bf16.f32 "
                "{%0,%1,%2,%3},{%4,%5,%6,%7},{%8,%9},{%0,%1,%2,%3};"
                : "+f"(c[2 * j + 1][0]), "+f"(c[2 * j + 1][1]),
                  "+f"(c[2 * j + 1][2]), "+f"(c[2 * j + 1][3])
                : "r"(a0), "r"(a1), "r"(a2), "r"(a3), "r"(b2), "r"(b3));
        }
        baddr += 32;
    }

    const int p_lo = tile * 128 + m0 + (lane >> 2);
    const bool v_lo = p_lo < 3136, v_hi = (p_lo + 8) < 3136;
#pragma unroll
    for (int nt = 0; nt < 8; nt++) {
        int n = nt * 8 + (lane & 3) * 2;
        float bi0 = sbias[n], bi1 = sbias[n + 1];
        float s0 = (v_lo ? fmaxf(c[nt][0] + bi0, 0.f) : 0.f)
                 + (v_hi ? fmaxf(c[nt][2] + bi0, 0.f) : 0.f);
        float s1 = (v_lo ? fmaxf(c[nt][1] + bi1, 0.f) : 0.f)
                 + (v_hi ? fmaxf(c[nt][3] + bi1, 0.f) : 0.f);
#pragma unroll
        for (int off = 4; off < 32; off <<= 1) {
            s0 += __shfl_xor_sync(0xFFFFFFFFu, s0, off);
            s1 += __shfl_xor_sync(0xFFFFFFFFu, s1, off);
        }
        if (lane < 4) {
            spool[wid * 64 + n]     = s0;
            spool[wid * 64 + n + 1] = s1;
        }
    }
    __syncthreads();
    if (tid < 64) {
        float s = 0.f;
#pragma unroll
        for (int g = 0; g < 8; g++) s += spool[g * 64 + tid];
        g_pool[(b * 25 + tile) * 64 + tid] = s;
    }
}

// ===========================================================================
// K3: per-sample. Logits with fixed-trip unrolled segments; d2 warp-parallel.
// ===========================================================================
__global__ void k_sample(const float* __restrict__ fcfw, const float* __restrict__ fcfb,
                         const float* __restrict__ fccw, const float* __restrict__ fccb) {
    __shared__ float spool[64];
    __shared__ float sfeat[FEAT];
    __shared__ float slogp[3][NC];
    __shared__ float slog[NC];
    __shared__ float sd2[32];
    __shared__ float sAn[25];
    const int b = blockIdx.x, tid = threadIdx.x;
    const int wid = tid >> 5, lane = tid & 31;

    if (tid < 64) {
        float s = 0.f;
#pragma unroll
        for (int rg = 0; rg < 25; rg++) s += g_pool[(b * 25 + rg) * 64 + tid];
        spool[tid] = s * (1.f / (HW2 * HW2));
    }
    __syncthreads();

    for (int j = tid; j < FEAT; j += 256) {
        float acc = fcfb[j];
#pragma unroll 8
        for (int i = 0; i < 64; i++) acc += spool[i] * fcfw[i * FEAT + j];
        sfeat[j] = fmaxf(acc, 0.f);
    }
    __syncthreads();

    // logits: 3 fixed-trip segments of 344, unrolled for MLP
    if (tid < 240) {
        int c = tid % NC, s = tid / NC;
        int fs = s * 344;
        float acc = 0.f;
#pragma unroll 8
        for (int k = 0; k < 344; k++) {
            int f = fs + k;
            if (f < FEAT) acc += sfeat[f] * fccw[f * NC + c];
        }
        slogp[s][c] = acc;
    }

    // d2: one warp per pair, lanes over f, shfl reduce
#pragma unroll 1
    for (int p = wid; p < 25; p += 8) {
        int i = p / 5, j = p % 5;
        float s = 0.f;
#pragma unroll 4
        for (int it = 0; it < 32; it++) {
            int f = lane + 32 * it;
            float xi = (i == 0) ? sfeat[f] : ((f < 256) ? sfeat[(i - 1) * 256 + f] : 0.f);
            float xj = (j == 0) ? sfeat[f] : ((f < 256) ? sfeat[(j - 1) * 256 + f] : 0.f);
            float d = xi - xj; s += d * d;
        }
#pragma unroll
        for (int off = 16; off > 0; off >>= 1) s += __shfl_xor_sync(0xFFFFFFFFu, s, off);
        if (lane == 0) sd2[p] = s;
    }
    __syncthreads();
    if (tid < NC) slog[tid] = slogp[0][tid] + slogp[1][tid] + slogp[2][tid] + fccb[tid];
    __syncthreads();

    if (tid == 0) {
        int i1 = 0;
        for (int c = 1; c < NC; c++) if (slog[c] > slog[i1]) i1 = c;
        int i2 = (i1 == 0) ? 1 : 0;
        for (int c = 0; c < NC; c++) if (c != i1 && slog[c] > slog[i2]) i2 = c;
        g_top[b * 2] = i1; g_top[b * 2 + 1] = i2;

        float A[5][5];
        for (int t = 0; t < 5; t++) for (int s = 0; s < 5; s++) A[t][s] = 0.f;
        for (int t = 0; t < 5; t++) {
            bool used[5] = {false, false, false, false, false};
            for (int k = 0; k < 4; k++) {
                int best = -1; float bd = 1e30f;
                for (int s = 0; s < 5; s++)
                    if (!used[s] && sd2[t * 5 + s] < bd) { bd = sd2[t * 5 + s]; best = s; }
                used[best] = true; A[t][best] = 1.f;
            }
        }
        for (int t = 0; t < 5; t++)
            for (int s = 0; s < 5; s++) g_A[b * 25 + t * 5 + s] = A[t][s];

        float dinv[5];
        for (int t = 0; t < 5; t++) {
            float deg = 0.f;
            for (int s = 0; s < 5; s++) deg += A[t][s] + (s == t ? 1.f : 0.f);
            dinv[t] = deg > 0.f ? rsqrtf(deg) : 0.f;
        }
        for (int t = 0; t < 5; t++)
            for (int s = 0; s < 5; s++)
                sAn[t * 5 + s] = (A[t][s] + (s == t ? 1.f : 0.f)) * dinv[t] * dinv[s];
        for (int s = 0; s < 5; s++) {
            float ab = 0.f;
            for (int t = 0; t < 5; t++) ab += sAn[t * 5 + s];
            g_abar[b * 5 + s] = 0.2f * ab;
        }
    }
    __syncthreads();

    for (int f = tid; f < FEAT; f += 256) {
        float xs[5];
        xs[0] = sfeat[f];
#pragma unroll
        for (int s = 1; s < 5; s++) xs[s] = (f < 256) ? sfeat[(s - 1) * 256 + f] : 0.f;
#pragma unroll
        for (int t = 0; t < 5; t++) {
            float a = 0.f;
#pragma unroll
            for (int s = 0; s < 5; s++) a += sAn[t * 5 + s] * xs[s];
            g_agg[(b * 5 + t) * FEAT + f] = a;
        }
    }
}

// ===========================================================================
// K4a: expert h1 partials (f-split x8 -> 1024 blocks). K4b: reduce + w2 GEMM.
// ===========================================================================
__global__ void k_exp1(const float* __restrict__ w1) {
    __shared__ float sagg[5][128];
    const int blk = blockIdx.x, b = blk >> 1, k = blk & 1;
    const int sl = blockIdx.y, f0 = sl * 128;
    const int tid = threadIdx.x;
    const int e = g_top[b * 2 + k];

    for (int i = tid; i < 5 * 128; i += 256)
        sagg[i >> 7][i & 127] = g_agg[(b * 5 + (i >> 7)) * FEAT + f0 + (i & 127)];
    __syncthreads();

    u64 acc[5];
#pragma unroll
    for (int t = 0; t < 5; t++) acc[t] = 0ULL;
    const float2* wrow = (const float2*)(w1 + ((size_t)e * FEAT + f0) * HID) + tid;
#pragma unroll 8
    for (int f = 0; f < 128; f++) {
        u64 wv = *(const u64*)(wrow + f * (HID / 2));
#pragma unroll
        for (int t = 0; t < 5; t++) fma2(acc[t], pk2(sagg[t][f]), wv);
    }
    float* dst = &g_h1p[((blk * 8 + sl) * 5) * HID + 2 * tid];
#pragma unroll
    for (int t = 0; t < 5; t++) {
        float a0, a1; upk(acc[t], a0, a1);
        *(float2*)(dst + t * HID) = make_float2(a0, a1);
    }
}

__global__ void k_exp2(const float* __restrict__ b1,
                       const float* __restrict__ w2, const float* __restrict__ b2) {
    __shared__ float shb[HID];
    __shared__ float sred[512];
    const int blk = blockIdx.x, b = blk >> 1, k = blk & 1;
    const int tid = threadIdx.x;
    const int e = g_top[b * 2 + k];

    if (tid < 256) {
        const int h0 = 2 * tid;
        float s0[5], s1[5];
#pragma unroll
        for (int t = 0; t < 5; t++) { s0[t] = 0.f; s1[t] = 0.f; }
#pragma unroll
        for (int sl = 0; sl < 8; sl++)
#pragma unroll
            for (int t = 0; t < 5; t++) {
                float2 v = *(const float2*)&g_h1p[((blk * 8 + sl) * 5 + t) * HID + h0];
                s0[t] += v.x; s1[t] += v.y;
            }
        const float bb0 = b1[e * HID + h0], bb1 = b1[e * HID + h0 + 1];
        float hb0 = 0.f, hb1 = 0.f;
#pragma unroll
        for (int t = 0; t < 5; t++) {
            float ab = g_abar[b * 5 + t];
            hb0 += ab * fmaxf(s0[t] + bb0, 0.f);
            hb1 += ab * fmaxf(s1[t] + bb1, 0.f);
        }
        shb[h0] = hb0; shb[h0 + 1] = hb1;
    }
    __syncthreads();

    const int o = tid & 255, half = tid >> 8;
    const float* w2e = w2 + (size_t)e * HID * OUTD + (size_t)half * 256 * OUTD + o;
    float acc = 0.f;
#pragma unroll 8
    for (int h = 0; h < 256; h++) acc += shb[half * 256 + h] * w2e[h * OUTD];
    sred[tid] = acc;
    __syncthreads();
    if (tid < 256)
        g_g[blk * OUTD + o] = sred[tid] + sred[tid + 256] + b2[e * OUTD + o];
}

// ===========================================================================
// K5: final GCN + expert mean.
// ===========================================================================
__global__ void k_final(const float* __restrict__ finw, const float* __restrict__ finb,
                        float* __restrict__ out) {
    __shared__ float sg[2][OUTD];
    __shared__ float sg5[5][OUTD];
    __shared__ float sPn[2][NC];
    __shared__ float sP5[5][NC];
    __shared__ float sA63[25];
    const int b = blockIdx.x, tid = threadIdx.x;
    const int n0 = 2 * b;
    const bool need5 = (b <= 2);

    for (int i = tid; i < 2 * OUTD; i += 160) ((float*)sg)[i] = g_g[n0 * OUTD + i];
    if (need5) {
        for (int i = tid; i < 5 * OUTD; i += 160) ((float*)sg5)[i] = g_g[i];
        if (tid < 25) sA63[tid] = g_A[63 * 25 + tid];
    }
    __syncthreads();

    {
        int ni = tid / 80, c = tid % 80;
        float acc = 0.f;
#pragma unroll 4
        for (int o = 0; o < OUTD; o++) acc += sg[ni][o] * finw[o * NC + c];
        sPn[ni][c] = acc;
    }
    if (need5) {
        for (int idx = tid; idx < 5 * 80; idx += 160) {
            int m = idx / 80, c = idx % 80;
            float acc = 0.f;
#pragma unroll 4
            for (int o = 0; o < OUTD; o++) acc += sg5[m][o] * finw[o * NC + c];
            sP5[m][c] = acc;
        }
    }
    __syncthreads();

    if (tid < 80) {
        const int c = tid;
        float f01[2];
#pragma unroll
        for (int i = 0; i < 2; i++) {
            int n = n0 + i;
            if (n < 5) {
                float s = 0.f;
                for (int m = 0; m < 5; m++)
                    s += ((m == n ? 1.f : 0.f) + sA63[n * 5 + m]) * sP5[m][c];
                f01[i] = 0.2f * s;
            } else {
                f01[i] = sPn[i][c];
            }
        }
        out[b * NC + c] = 0.5f * (f01[0] + f01[1]) + finb[c];
    }
}

// ===========================================================================
extern "C" void kernel_launch(void* const* d_in, const int* in_sizes, int n_in,
                              void* d_out, int out_size) {
    const float* x    = (const float*)d_in[0];
    const float* c1w  = (const float*)d_in[1];
    const float* c1b  = (const float*)d_in[2];
    const float* c2w  = (const float*)d_in[3];
    const float* c2b  = (const float*)d_in[4];
    const float* fcfw = (const float*)d_in[5];
    const float* fcfb = (const float*)d_in[6];
    const float* fccw = (const float*)d_in[7];
    const float* fccb = (const float*)d_in[8];
    const float* gw1  = (const float*)d_in[9];
    const float* gb1  = (const float*)d_in[10];
    const float* gw2  = (const float*)d_in[11];
    const float* gb2  = (const float*)d_in[12];
    const float* finw = (const float*)d_in[13];
    const float* finb = (const float*)d_in[14];
    float* out = (float*)d_out;

    cudaFuncSetAttribute(k_conv2, cudaFuncAttributeMaxDynamicSharedMemorySize, SMEMC);

    k_conv1<<<dim3(56, 64), 224>>>(x, c1w, c1b);
    k_prep<<<1, 256>>>(c2w);
    k_conv2<<<dim3(25, 64), 256, SMEMC>>>(c2b);
    k_sample<<<64, 256>>>(fcfw, fcfb, fccw, fccb);
    k_exp1<<<dim3(128, 8), 256>>>(gw1);
    k_exp2<<<128, 512>>>(gb1, gw2, gb2);
    k_final<<<64, 160>>>(finw, finb, out);
    (void)in_sizes; (void)n_in; (void)out_size;
}

// round 12
// speedup vs baseline: 1.6080x; 1.6080x over previous
#include <cuda_runtime.h>
#include <cuda_bf16.h>
#include <cstdint>

typedef unsigned int u32;
typedef unsigned long long u64;

#define B_    64
#define IMG   224
#define HW1   112
#define HW2   56
#define FEAT  1024
#define HID   512
#define OUTD  256
#define NC    80

#define APAD  296              // padded K stride in bf16 (592 B, conflict-free)

// ---------------- scratch (static device globals) --------------------------
__device__ __nv_bfloat16 g_conv1b[B_ * HW1 * HW1 * 32];  // NHWC bf16 conv1 out
__device__ __nv_bfloat16 g_wb[64 * APAD];                // conv2 weights bf16 [oc][k]
__device__ float g_pool[B_ * 25 * 64];                   // GAP partials per tile
__device__ float g_feat[B_ * FEAT];                      // relu'd features
__device__ int   g_top[B_ * 2];
__device__ float g_A[B_ * 25];
__device__ float g_abar[B_ * 5];
__device__ float g_agg[B_ * 5 * FEAT];
__device__ float g_h1p[128 * 4 * 5 * HID];               // pre-relu h1 partials
__device__ float g_g[B_ * 2 * OUTD];

// ---------------- f32x2 helpers (expert GEMM only) -------------------------
__device__ __forceinline__ u64 pk2(float v) {
    u64 r; asm("mov.b64 %0,{%1,%1};" : "=l"(r) : "f"(v)); return r;
}
__device__ __forceinline__ void upk(u64 v, float& a, float& b) {
    asm("mov.b64 {%0,%1},%2;" : "=f"(a), "=f"(b) : "l"(v));
}
__device__ __forceinline__ void fma2(u64& d, u64 a, u64 b) {
    asm("fma.rn.f32x2 %0,%1,%2,%3;" : "=l"(d) : "l"(a), "l"(b), "l"(d));
}

__device__ __forceinline__ u32 smem_u32(const void* p) {
    u32 a;
    asm("{ .reg .u64 t; cvta.to.shared.u64 t, %1; cvt.u32.u64 %0, t; }"
        : "=r"(a) : "l"(p));
    return a;
}

// ===========================================================================
// K1: conv1 3->32 s2 SAME relu, scalar fp32 FFMA (R5 measured-good version),
// output bf16 NHWC.
// ===========================================================================
__global__ __launch_bounds__(224) void k_conv1(const float* __restrict__ x,
                                               const float* __restrict__ w,
                                               const float* __restrict__ bias) {
    __shared__ float  sx[3][5][226];
    __shared__ float4 w4[27][8];
    __shared__ float  sb[32];
    const int b = blockIdx.y, r0 = blockIdx.x * 2;
    const int tid = threadIdx.x;

    for (int idx = tid; idx < 3 * 5 * 226; idx += 224) {
        int ic = idx / (5 * 226);
        int rem = idx % (5 * 226);
        int rr = rem / 226, col = rem % 226;
        int gr = 2 * r0 + rr;
        float v = 0.f;
        if (gr < IMG && col < IMG) v = x[((b * 3 + ic) * IMG + gr) * IMG + col];
        sx[ic][rr][col] = v;
    }
    if (tid < 216) {
        int ip = tid / 8, ov = tid & 7;
        int ic = ip / 9, kh = (ip / 3) % 3, kw = ip % 3;
        w4[ip][ov] = make_float4(
            w[(((4 * ov + 0) * 3 + ic) * 3 + kh) * 3 + kw],
            w[(((4 * ov + 1) * 3 + ic) * 3 + kh) * 3 + kw],
            w[(((4 * ov + 2) * 3 + ic) * 3 + kh) * 3 + kw],
            w[(((4 * ov + 3) * 3 + ic) * 3 + kh) * 3 + kw]);
    }
    if (tid < 32) sb[tid] = bias[tid];
    __syncthreads();

    const int rr = tid / 112, c = tid % 112;
    const int r = r0 + rr;
    float acc[32];
#pragma unroll
    for (int i = 0; i < 32; i++) acc[i] = 0.f;

#pragma unroll
    for (int ic = 0; ic < 3; ic++)
#pragma unroll
        for (int kh = 0; kh < 3; kh++) {
            float av[3] = {sx[ic][2 * rr + kh][2 * c],
                           sx[ic][2 * rr + kh][2 * c + 1],
                           sx[ic][2 * rr + kh][2 * c + 2]};
#pragma unroll
            for (int kw = 0; kw < 3; kw++) {
                float a = av[kw];
#pragma unroll
                for (int ov = 0; ov < 8; ov++) {
                    float4 wv = w4[ic * 9 + kh * 3 + kw][ov];
                    acc[4 * ov + 0] += a * wv.x;
                    acc[4 * ov + 1] += a * wv.y;
                    acc[4 * ov + 2] += a * wv.z;
                    acc[4 * ov + 3] += a * wv.w;
                }
            }
        }

    u32 pk[16];
#pragma unroll
    for (int i = 0; i < 16; i++) {
        float lo = fmaxf(acc[2 * i] + sb[2 * i], 0.f);
        float hi = fmaxf(acc[2 * i + 1] + sb[2 * i + 1], 0.f);
        __nv_bfloat162 t = __floats2bfloat162_rn(lo, hi);
        pk[i] = *(u32*)&t;
    }
    uint4* dst = (uint4*)(g_conv1b + (size_t)((b * HW1 + r) * HW1 + c) * 32);
#pragma unroll
    for (int j = 0; j < 4; j++)
        dst[j] = make_uint4(pk[4 * j], pk[4 * j + 1], pk[4 * j + 2], pk[4 * j + 3]);
}

// ===========================================================================
// K_prep: conv2 weights -> bf16 [oc][k], k = (kh*3+kw)*32 + ic.
// ===========================================================================
__global__ void k_prep(const float* __restrict__ w) {
    const int tid = threadIdx.x;
    for (int idx = tid; idx < 64 * 288; idx += 256) {
        int oc = idx / 288, k = idx % 288;
        int q = k >> 5, ic = k & 31;
        g_wb[oc * APAD + k] = __float2bfloat16(w[oc * 288 + ic * 9 + q]);
    }
}

// ===========================================================================
// K2: conv2 as HMMA GEMM (R5 measured-good version, unchanged).
// ===========================================================================
#define SMA_B   (128 * APAD * 2)
#define SMB_B   (64 * APAD * 2)
#define SMEMC   (SMA_B + SMB_B + 256 + 2048)

__global__ __launch_bounds__(256) void k_conv2(const float* __restrict__ bias) {
    extern __shared__ char sm[];
    char*  smA   = sm;
    char*  smB   = sm + SMA_B;
    float* sbias = (float*)(sm + SMA_B + SMB_B);
    float* spool = (float*)(sm + SMA_B + SMB_B + 256);

    const int b = blockIdx.y, tile = blockIdx.x;
    const int tid = threadIdx.x, wid = tid >> 5, lane = tid & 31;

    for (int t = tid; t < 64 * 9; t += 256) {
        int oc = t / 9, q = t % 9;
        const uint4* src = (const uint4*)(g_wb + oc * APAD + q * 32);
        uint4* dst = (uint4*)(smB + oc * (APAD * 2) + q * 64);
        dst[0] = src[0]; dst[1] = src[1]; dst[2] = src[2]; dst[3] = src[3];
    }
    if (tid < 64) sbias[tid] = bias[tid];

    for (int t = tid; t < 9 * 128; t += 256) {
        int pixel = t & 127, q = t >> 7;
        int kh = q / 3, kw = q % 3;
        int p = tile * 128 + pixel;
        uint4 v0 = {0,0,0,0}, v1 = {0,0,0,0}, v2 = {0,0,0,0}, v3 = {0,0,0,0};
        if (p < 3136) {
            int r = p / 56, c = p - 56 * r;
            int ir = 2 * r + kh, icc = 2 * c + kw;
            if (ir < HW1 && icc < HW1) {
                const uint4* src =
                    (const uint4*)(g_conv1b + (size_t)((b * HW1 + ir) * HW1 + icc) * 32);
                v0 = src[0]; v1 = src[1]; v2 = src[2]; v3 = src[3];
            }
        }
        uint4* dst = (uint4*)(smA + pixel * (APAD * 2) + q * 64);
        dst[0] = v0; dst[1] = v1; dst[2] = v2; dst[3] = v3;
    }
    __syncthreads();

    const int m0 = wid * 16;
    float c[8][4];
#pragma unroll
    for (int i = 0; i < 8; i++)
#pragma unroll
        for (int j = 0; j < 4; j++) c[i][j] = 0.f;

    u32 aaddr = smem_u32(smA) + (m0 + (lane & 15)) * (APAD * 2) + ((lane >> 4) * 16);
    u32 baddr = smem_u32(smB) + ((lane & 7) + ((lane >> 4) & 1) * 8) * (APAD * 2)
              + (((lane >> 3) & 1) * 16);

#pragma unroll 2
    for (int ks = 0; ks < 18; ks++) {
        u32 a0, a1, a2, a3;
        asm volatile("ldmatrix.sync.aligned.m8n8.x4.shared.b16 {%0,%1,%2,%3},[%4];"
                     : "=r"(a0), "=r"(a1), "=r"(a2), "=r"(a3) : "r"(aaddr));
        aaddr += 32;
#pragma unroll
        for (int j = 0; j < 4; j++) {
            u32 b0, b1, b2, b3;
            asm volatile("ldmatrix.sync.aligned.m8n8.x4.shared.b16 {%0,%1,%2,%3},[%4];"
                         : "=r"(b0), "=r"(b1), "=r"(b2), "=r"(b3)
                         : "r"(baddr + j * (16 * APAD * 2)));
            asm volatile(
                "mma.sync.aligned.m16n8k16.row.col.f32.bf16.bf16.f32 "
                "{%0,%1,%2,%3},{%4,%5,%6,%7},{%8,%9},{%0,%1,%2,%3};"
                : "+f"(c[2 * j][0]), "+f"(c[2 * j][1]),
                  "+f"(c[2 * j][2]), "+f"(c[2 * j][3])
                : "r"(a0), "r"(a1), "r"(a2), "r"(a3), "r"(b0), "r"(b1));
            asm volatile(
                "mma.sync.aligned.m16n8k16.row.col.f32.bf16.bf16.f32 "
                "{%0,%1,%2,%3},{%4,%5,%6,%7},{%8,%9},{%0,%1,%2,%3};"
                : "+f"(c[2 * j + 1][0]), "+f"(c[2 * j + 1][1]),
                  "+f"(c[2 * j + 1][2]), "+f"(c[2 * j + 1][3])
                : "r"(a0), "r"(a1), "r"(a2), "r"(a3), "r"(b2), "r"(b3));
        }
        baddr += 32;
    }

    const int p_lo = tile * 128 + m0 + (lane >> 2);
    const bool v_lo = p_lo < 3136, v_hi = (p_lo + 8) < 3136;
#pragma unroll
    for (int nt = 0; nt < 8; nt++) {
        int n = nt * 8 + (lane & 3) * 2;
        float bi0 = sbias[n], bi1 = sbias[n + 1];
        float s0 = (v_lo ? fmaxf(c[nt][0] + bi0, 0.f) : 0.f)
                 + (v_hi ? fmaxf(c[nt][2] + bi0, 0.f) : 0.f);
        float s1 = (v_lo ? fmaxf(c[nt][1] + bi1, 0.f) : 0.f)
                 + (v_hi ? fmaxf(c[nt][3] + bi1, 0.f) : 0.f);
#pragma unroll
        for (int off = 4; off < 32; off <<= 1) {
            s0 += __shfl_xor_sync(0xFFFFFFFFu, s0, off);
            s1 += __shfl_xor_sync(0xFFFFFFFFu, s1, off);
        }
        if (lane < 4) {
            spool[wid * 64 + n]     = s0;
            spool[wid * 64 + n + 1] = s1;
        }
    }
    __syncthreads();
    if (tid < 64) {
        float s = 0.f;
#pragma unroll
        for (int g = 0; g < 8; g++) s += spool[g * 64 + tid];
        g_pool[(b * 25 + tile) * 64 + tid] = s;
    }
}

// ===========================================================================
// K_feat: grid (64, 4). Block (b, sl) computes feats[sl*256 .. +256) for
// sample b: GAP reduce (redundant per slice, cheap) + FC + relu -> g_feat.
// 4x the block parallelism of the old fused front end.
// ===========================================================================
__global__ __launch_bounds__(256) void k_feat(const float* __restrict__ fcfw,
                                              const float* __restrict__ fcfb) {
    __shared__ float spool[64];
    const int b = blockIdx.x, j0 = blockIdx.y * 256;
    const int tid = threadIdx.x;

    if (tid < 64) {
        float s = 0.f;
#pragma unroll
        for (int rg = 0; rg < 25; rg++) s += g_pool[(b * 25 + rg) * 64 + tid];
        spool[tid] = s * (1.f / (HW2 * HW2));
    }
    __syncthreads();

    const int j = j0 + tid;
    float acc = fcfb[j];
#pragma unroll 8
    for (int i = 0; i < 64; i++) acc += spool[i] * fcfw[i * FEAT + j];
    g_feat[b * FEAT + j] = fmaxf(acc, 0.f);
}

// ===========================================================================
// K3: per-sample graph kernel, 512 threads. Loads g_feat to smem; logits as
// 6 f-segments x 80 classes; d2 over 16 warps; serial top-k/knn/gcn-norm;
// agg over 512 lanes.
// ===========================================================================
__global__ __launch_bounds__(512) void k_sample(const float* __restrict__ fccw,
                                                const float* __restrict__ fccb) {
    __shared__ float sfeat[FEAT];
    __shared__ float slogp[6][NC];
    __shared__ float slog[NC];
    __shared__ float sd2[32];
    __shared__ float sAn[25];
    const int b = blockIdx.x, tid = threadIdx.x;
    const int wid = tid >> 5, lane = tid & 31;

    sfeat[tid] = g_feat[b * FEAT + tid];
    sfeat[tid + 512] = g_feat[b * FEAT + tid + 512];
    __syncthreads();

    // logits: 6 fixed segments (5x171 + 1x169), c = tid%80
    if (tid < 480) {
        int c = tid % NC, s = tid / NC;
        int fs = s * 171;
        int n = (s == 5) ? 169 : 171;
        float acc = 0.f;
#pragma unroll 8
        for (int k = 0; k < 171; k++) {
            if (k < n) acc += sfeat[fs + k] * fccw[(fs + k) * NC + c];
        }
        slogp[s][c] = acc;
    }

    // d2: one warp per pair (16 warps, 25 pairs -> <=2 per warp)
#pragma unroll 1
    for (int p = wid; p < 25; p += 16) {
        int i = p / 5, j = p % 5;
        float s = 0.f;
#pragma unroll 4
        for (int it = 0; it < 32; it++) {
            int f = lane + 32 * it;
            float xi = (i == 0) ? sfeat[f] : ((f < 256) ? sfeat[(i - 1) * 256 + f] : 0.f);
            float xj = (j == 0) ? sfeat[f] : ((f < 256) ? sfeat[(j - 1) * 256 + f] : 0.f);
            float d = xi - xj; s += d * d;
        }
#pragma unroll
        for (int off = 16; off > 0; off >>= 1) s += __shfl_xor_sync(0xFFFFFFFFu, s, off);
        if (lane == 0) sd2[p] = s;
    }
    __syncthreads();
    if (tid < NC)
        slog[tid] = slogp[0][tid] + slogp[1][tid] + slogp[2][tid]
                  + slogp[3][tid] + slogp[4][tid] + slogp[5][tid] + fccb[tid];
    __syncthreads();

    if (tid == 0) {
        int i1 = 0;
        for (int c = 1; c < NC; c++) if (slog[c] > slog[i1]) i1 = c;
        int i2 = (i1 == 0) ? 1 : 0;
        for (int c = 0; c < NC; c++) if (c != i1 && slog[c] > slog[i2]) i2 = c;
        g_top[b * 2] = i1; g_top[b * 2 + 1] = i2;

        float A[5][5];
        for (int t = 0; t < 5; t++) for (int s = 0; s < 5; s++) A[t][s] = 0.f;
        for (int t = 0; t < 5; t++) {
            bool used[5] = {false, false, false, false, false};
            for (int k = 0; k < 4; k++) {
                int best = -1; float bd = 1e30f;
                for (int s = 0; s < 5; s++)
                    if (!used[s] && sd2[t * 5 + s] < bd) { bd = sd2[t * 5 + s]; best = s; }
                used[best] = true; A[t][best] = 1.f;
            }
        }
        for (int t = 0; t < 5; t++)
            for (int s = 0; s < 5; s++) g_A[b * 25 + t * 5 + s] = A[t][s];

        float dinv[5];
        for (int t = 0; t < 5; t++) {
            float deg = 0.f;
            for (int s = 0; s < 5; s++) deg += A[t][s] + (s == t ? 1.f : 0.f);
            dinv[t] = deg > 0.f ? rsqrtf(deg) : 0.f;
        }
        for (int t = 0; t < 5; t++)
            for (int s = 0; s < 5; s++)
                sAn[t * 5 + s] = (A[t][s] + (s == t ? 1.f : 0.f)) * dinv[t] * dinv[s];
        for (int s = 0; s < 5; s++) {
            float ab = 0.f;
            for (int t = 0; t < 5; t++) ab += sAn[t * 5 + s];
            g_abar[b * 5 + s] = 0.2f * ab;
        }
    }
    __syncthreads();

    // agg = An @ Xg, 512 threads x 2 f each
#pragma unroll
    for (int rep = 0; rep < 2; rep++) {
        int f = tid + rep * 512;
        float xs[5];
        xs[0] = sfeat[f];
#pragma unroll
        for (int s = 1; s < 5; s++) xs[s] = (f < 256) ? sfeat[(s - 1) * 256 + f] : 0.f;
#pragma unroll
        for (int t = 0; t < 5; t++) {
            float a = 0.f;
#pragma unroll
            for (int s = 0; s < 5; s++) a += sAn[t * 5 + s] * xs[s];
            g_agg[(b * 5 + t) * FEAT + f] = a;
        }
    }
}

// ===========================================================================
// K4a: expert h1 partials (f-split x4, R3 measured-good config).
// ===========================================================================
__global__ void k_exp1(const float* __restrict__ w1) {
    __shared__ float sagg[5][256];
    const int blk = blockIdx.x, b = blk >> 1, k = blk & 1;
    const int sl = blockIdx.y, f0 = sl * 256;
    const int tid = threadIdx.x;
    const int e = g_top[b * 2 + k];

    for (int i = tid; i < 5 * 256; i += 256)
        sagg[i >> 8][i & 255] = g_agg[(b * 5 + (i >> 8)) * FEAT + f0 + (i & 255)];
    __syncthreads();

    u64 acc[5];
#pragma unroll
    for (int t = 0; t < 5; t++) acc[t] = 0ULL;
    const float2* wrow = (const float2*)(w1 + ((size_t)e * FEAT + f0) * HID) + tid;
#pragma unroll 8
    for (int f = 0; f < 256; f++) {
        u64 wv = *(const u64*)(wrow + f * (HID / 2));
#pragma unroll
        for (int t = 0; t < 5; t++) fma2(acc[t], pk2(sagg[t][f]), wv);
    }
    float* dst = &g_h1p[((blk * 4 + sl) * 5) * HID + 2 * tid];
#pragma unroll
    for (int t = 0; t < 5; t++) {
        float a0, a1; upk(acc[t], a0, a1);
        *(float2*)(dst + t * HID) = make_float2(a0, a1);
    }
}

__global__ void k_exp2(const float* __restrict__ b1,
                       const float* __restrict__ w2, const float* __restrict__ b2) {
    __shared__ float shb[HID];
    __shared__ float sred[512];
    const int blk = blockIdx.x, b = blk >> 1, k = blk & 1;
    const int tid = threadIdx.x;
    const int e = g_top[b * 2 + k];

    if (tid < 256) {
        const int h0 = 2 * tid;
        float s0[5], s1[5];
#pragma unroll
        for (int t = 0; t < 5; t++) { s0[t] = 0.f; s1[t] = 0.f; }
#pragma unroll
        for (int sl = 0; sl < 4; sl++)
#pragma unroll
            for (int t = 0; t < 5; t++) {
                float2 v = *(const float2*)&g_h1p[((blk * 4 + sl) * 5 + t) * HID + h0];
                s0[t] += v.x; s1[t] += v.y;
            }
        const float bb0 = b1[e * HID + h0], bb1 = b1[e * HID + h0 + 1];
        float hb0 = 0.f, hb1 = 0.f;
#pragma unroll
        for (int t = 0; t < 5; t++) {
            float ab = g_abar[b * 5 + t];
            hb0 += ab * fmaxf(s0[t] + bb0, 0.f);
            hb1 += ab * fmaxf(s1[t] + bb1, 0.f);
        }
        shb[h0] = hb0; shb[h0 + 1] = hb1;
    }
    __syncthreads();

    const int o = tid & 255, half = tid >> 8;
    const float* w2e = w2 + (size_t)e * HID * OUTD + (size_t)half * 256 * OUTD + o;
    float acc = 0.f;
#pragma unroll 8
    for (int h = 0; h < 256; h++) acc += shb[half * 256 + h] * w2e[h * OUTD];
    sred[tid] = acc;
    __syncthreads();
    if (tid < 256)
        g_g[blk * OUTD + o] = sred[tid] + sred[tid + 256] + b2[e * OUTD + o];
}

// ===========================================================================
// K5: final GCN + expert mean.
// ===========================================================================
__global__ void k_final(const float* __restrict__ finw, const float* __restrict__ finb,
                        float* __restrict__ out) {
    __shared__ float sg[2][OUTD];
    __shared__ float sg5[5][OUTD];
    __shared__ float sPn[2][NC];
    __shared__ float sP5[5][NC];
    __shared__ float sA63[25];
    const int b = blockIdx.x, tid = threadIdx.x;
    const int n0 = 2 * b;
    const bool need5 = (b <= 2);

    for (int i = tid; i < 2 * OUTD; i += 160) ((float*)sg)[i] = g_g[n0 * OUTD + i];
    if (need5) {
        for (int i = tid; i < 5 * OUTD; i += 160) ((float*)sg5)[i] = g_g[i];
        if (tid < 25) sA63[tid] = g_A[63 * 25 + tid];
    }
    __syncthreads();

    {
        int ni = tid / 80, c = tid % 80;
        float acc = 0.f;
#pragma unroll 4
        for (int o = 0; o < OUTD; o++) acc += sg[ni][o] * finw[o * NC + c];
        sPn[ni][c] = acc;
    }
    if (need5) {
        for (int idx = tid; idx < 5 * 80; idx += 160) {
            int m = idx / 80, c = idx % 80;
            float acc = 0.f;
#pragma unroll 4
            for (int o = 0; o < OUTD; o++) acc += sg5[m][o] * finw[o * NC + c];
            sP5[m][c] = acc;
        }
    }
    __syncthreads();

    if (tid < 80) {
        const int c = tid;
        float f01[2];
#pragma unroll
        for (int i = 0; i < 2; i++) {
            int n = n0 + i;
            if (n < 5) {
                float s = 0.f;
                for (int m = 0; m < 5; m++)
                    s += ((m == n ? 1.f : 0.f) + sA63[n * 5 + m]) * sP5[m][c];
                f01[i] = 0.2f * s;
            } else {
                f01[i] = sPn[i][c];
            }
        }
        out[b * NC + c] = 0.5f * (f01[0] + f01[1]) + finb[c];
    }
}

// ===========================================================================
extern "C" void kernel_launch(void* const* d_in, const int* in_sizes, int n_in,
                              void* d_out, int out_size) {
    const float* x    = (const float*)d_in[0];
    const float* c1w  = (const float*)d_in[1];
    const float* c1b  = (const float*)d_in[2];
    const float* c2w  = (const float*)d_in[3];
    const float* c2b  = (const float*)d_in[4];
    const float* fcfw = (const float*)d_in[5];
    const float* fcfb = (const float*)d_in[6];
    const float* fccw = (const float*)d_in[7];
    const float* fccb = (const float*)d_in[8];
    const float* gw1  = (const float*)d_in[9];
    const float* gb1  = (const float*)d_in[10];
    const float* gw2  = (const float*)d_in[11];
    const float* gb2  = (const float*)d_in[12];
    const float* finw = (const float*)d_in[13];
    const float* finb = (const float*)d_in[14];
    float* out = (float*)d_out;

    cudaFuncSetAttribute(k_conv2, cudaFuncAttributeMaxDynamicSharedMemorySize, SMEMC);

    k_conv1<<<dim3(56, 64), 224>>>(x, c1w, c1b);
    k_prep<<<1, 256>>>(c2w);
    k_conv2<<<dim3(25, 64), 256, SMEMC>>>(c2b);
    k_feat<<<dim3(64, 4), 256>>>(fcfw, fcfb);
    k_sample<<<64, 512>>>(fccw, fccb);
    k_exp1<<<dim3(128, 4), 256>>>(gw1);
    k_exp2<<<128, 512>>>(gb1, gw2, gb2);
    k_final<<<64, 160>>>(finw, finb, out);
    (void)in_sizes; (void)n_in; (void)out_size;
}